// round 10
// baseline (speedup 1.0000x reference)
#include <cuda_runtime.h>
#include <cuda_bf16.h>
#include <cstdint>

typedef __nv_bfloat16 bf16;

// Problem dims: B=8, C=512, H=W=64 -> N=4096, att=512
#define NB 8
#define NC 512
#define NN_ 4096
#define ND 512

// ---------------- scratch (static device globals) ---------------------------
__device__ __align__(1024) bf16  g_hT [(size_t)NB * NN_ * NC];  // [b][n][c]
__device__ __align__(1024) bf16  g_qT [(size_t)NB * NN_ * ND];  // [b][n][d]
__device__ __align__(1024) bf16  g_kT [(size_t)NB * NN_ * ND];  // [b][m][d]
__device__ __align__(1024) bf16  g_v  [(size_t)NB * ND * NN_];  // [b][d][m]
__device__ __align__(1024) bf16  g_S  [(size_t)NB * NN_ * NN_]; // [b][n][m] (256MB)
__device__ __align__(1024) bf16  g_hfT[(size_t)NB * NN_ * ND];  // [b][n][d]
__device__ __align__(1024) bf16  g_wq [ND * NC];
__device__ __align__(1024) bf16  g_wk [ND * NC];
__device__ __align__(1024) bf16  g_wv [ND * NC];
__device__ __align__(1024) bf16  g_wp [NC * ND];
__device__ float2 g_stats[NB * 32];                             // per (b,g): mean, inv

// ---------------- helpers -----------------------------------------------------
__device__ __forceinline__ uint32_t smem_u32(const void* p) {
    uint32_t a;
    asm("{ .reg .u64 t; cvta.to.shared.u64 t, %1; cvt.u32.u64 %0, t; }" : "=r"(a) : "l"(p));
    return a;
}
__device__ __forceinline__ void cp_async16(uint32_t s, const void* g) {
    asm volatile("cp.async.cg.shared.global [%0], [%1], 16;" :: "r"(s), "l"(g));
}
#define CP_COMMIT()  asm volatile("cp.async.commit_group;" ::: "memory")
#define CP_WAIT1()   asm volatile("cp.async.wait_group 1;" ::: "memory")

__device__ __forceinline__ void ldm4(uint32_t* r, uint32_t addr) {
    asm volatile("ldmatrix.sync.aligned.m8n8.x4.shared.b16 {%0,%1,%2,%3}, [%4];"
        : "=r"(r[0]), "=r"(r[1]), "=r"(r[2]), "=r"(r[3]) : "r"(addr));
}
__device__ __forceinline__ void mma16816(float* d, const uint32_t* a, const uint32_t* b) {
    asm volatile(
        "mma.sync.aligned.m16n8k16.row.col.f32.bf16.bf16.f32 "
        "{%0,%1,%2,%3}, {%4,%5,%6,%7}, {%8,%9}, {%0,%1,%2,%3};"
        : "+f"(d[0]), "+f"(d[1]), "+f"(d[2]), "+f"(d[3])
        : "r"(a[0]), "r"(a[1]), "r"(a[2]), "r"(a[3]), "r"(b[0]), "r"(b[1]));
}

// ---------------- HMMA GEMM: D[M,N] = alpha * A[M,K] @ B[N,K]^T ---------------
// A, B bf16, K-contiguous (ldA=ldB=K), D row-major ld=N.
// CTA tile 128x256x64, 256 threads, 8 warps (2x4), warp tile 64x64.
// OM: 0 = bf16 out + col bias[n]; 1 = bf16 out + row bias[m];
//     2 = bf16 out * alpha;       4 = fp32 out + row bias[m] + residual.
#define BM 128
#define BN 256
#define BK 64
#define NT 256                      // threads per CTA
#define ROWB 144                    // padded row pitch in bytes (64 halves + 8 pad)
#define A_BYTES (BM * ROWB)         // 18432
#define B_BYTES (BN * ROWB)         // 36864
#define STAGE_BYTES (A_BYTES + B_BYTES) // 55296
#define STAGES 3
#define GEMM_SMEM (STAGES * STAGE_BYTES)

template<int OM>
__global__ __launch_bounds__(NT, 1)
void hm_gemm(const bf16* __restrict__ A, const bf16* __restrict__ B, void* __restrict__ Cv,
             const float* __restrict__ bias, const float* __restrict__ resid,
             int M, int N, int K,
             long long sA, long long sB, long long sC, long long sR, float alpha)
{
    extern __shared__ __align__(16) char smem[];
    int t = threadIdx.x, w = t >> 5, lane = t & 31;
    int wm = w >> 2, wn = w & 3;                  // 2 x 4 warps -> warp tile 64 x 64
    int bz = blockIdx.z;
    const bf16* Ab = A + sA * bz;
    const bf16* Bb = B + sB * bz;
    int bm = blockIdx.y * BM;
    int bn = blockIdx.x * BN;
    uint32_t sbase = smem_u32(smem);

    // per-stage tile load: A 128 rows x 8 chunks(16B) = 4/thr, B 256 rows = 8/thr
    auto load_chunk = [&](int kc, int s) {
        uint32_t sa = sbase + s * STAGE_BYTES;
        uint32_t sb = sa + A_BYTES;
        int k0 = kc * BK;
#pragma unroll
        for (int u = 0; u < 4; u++) {
            int idx = t + u * NT;
            int r = idx >> 3, c = idx & 7;
            cp_async16(sa + r * ROWB + c * 16, Ab + (size_t)(bm + r) * K + k0 + c * 8);
        }
#pragma unroll
        for (int u = 0; u < 8; u++) {
            int idx = t + u * NT;
            int r = idx >> 3, c = idx & 7;
            cp_async16(sb + r * ROWB + c * 16, Bb + (size_t)(bn + r) * K + k0 + c * 8);
        }
        CP_COMMIT();
    };

    // ldmatrix lane address offsets (bytes, relative to matrix base in stage)
    int lr = lane & 7, sub = lane >> 3;
    uint32_t offA = (uint32_t)((wm * 64 + (sub & 1) * 8 + lr) * ROWB + ((sub >> 1) * 8) * 2);
    uint32_t offB = (uint32_t)((wn * 64 + (sub >> 1) * 8 + lr) * ROWB + ((sub & 1) * 8) * 2);

    float acc[4][8][4];
#pragma unroll
    for (int i = 0; i < 4; i++)
#pragma unroll
        for (int j = 0; j < 8; j++)
#pragma unroll
            for (int q = 0; q < 4; q++) acc[i][j][q] = 0.f;

    uint32_t frA[2][4][4];   // [buf][m16 tile][4 regs]
    uint32_t frB[2][4][4];   // [buf][n16 grp][4 regs]; n8 op jj: grp jj>>1, regs (jj&1)*2..+1

    auto lds_frags = [&](uint32_t sb, int ks, int buf) {
        uint32_t ka = sb + offA + ks * 32;
#pragma unroll
        for (int i = 0; i < 4; i++) ldm4(frA[buf][i], ka + i * 16 * ROWB);
        uint32_t kb = sb + A_BYTES + offB + ks * 32;
#pragma unroll
        for (int j = 0; j < 4; j++) ldm4(frB[buf][j], kb + j * 16 * ROWB);
    };

    int nK = K / BK;
    load_chunk(0, 0); load_chunk(1, 1);

    int s = 0, sp = 2;
    for (int kc = 0; kc < nK; kc++) {
        CP_WAIT1();
        __syncthreads();
        if (kc + 2 < nK) load_chunk(kc + 2, sp);
        else CP_COMMIT();

        uint32_t sb = sbase + s * STAGE_BYTES;
        lds_frags(sb, 0, 0);
#pragma unroll
        for (int ks = 0; ks < 4; ks++) {
            if (ks < 3) lds_frags(sb, ks + 1, (ks + 1) & 1);
            int bu = ks & 1;
#pragma unroll
            for (int i = 0; i < 4; i++)
#pragma unroll
                for (int jj = 0; jj < 8; jj++)
                    mma16816(acc[i][jj], frA[bu][i], &frB[bu][jj >> 1][(jj & 1) * 2]);
        }
        s  = (s  == STAGES - 1) ? 0 : s + 1;
        sp = (sp == STAGES - 1) ? 0 : sp + 1;
    }

    // ---------------- epilogue: direct stores from accumulators ---------------
#pragma unroll
    for (int i = 0; i < 4; i++) {
        int r0 = bm + wm * 64 + i * 16 + (lane >> 2);
#pragma unroll
        for (int jj = 0; jj < 8; jj++) {
            int col = bn + wn * 64 + jj * 8 + (lane & 3) * 2;
            float v0 = acc[i][jj][0], v1 = acc[i][jj][1];
            float v2 = acc[i][jj][2], v3 = acc[i][jj][3];
            if (OM == 2) { v0 *= alpha; v1 *= alpha; v2 *= alpha; v3 *= alpha; }
            if (OM == 0) {
                float b0 = bias[col], b1 = bias[col + 1];
                v0 += b0; v1 += b1; v2 += b0; v3 += b1;
            }
            if (OM == 1 || OM == 4) {
                float ba = bias[r0], bb = bias[r0 + 8];
                v0 += ba; v1 += ba; v2 += bb; v3 += bb;
            }
            size_t o0 = (size_t)r0 * N + col;
            size_t o1 = (size_t)(r0 + 8) * N + col;
            if (OM == 4) {
                float* C = (float*)Cv + sC * bz;
                const float* R = resid + sR * bz;
                float2 ra = *(const float2*)&R[o0];
                float2 rb = *(const float2*)&R[o1];
                *(float2*)&C[o0] = make_float2(v0 + ra.x, v1 + ra.y);
                *(float2*)&C[o1] = make_float2(v2 + rb.x, v3 + rb.y);
            } else {
                bf16* C = (bf16*)Cv + sC * bz;
                __nv_bfloat162 p0 = __floats2bfloat162_rn(v0, v1);
                __nv_bfloat162 p1 = __floats2bfloat162_rn(v2, v3);
                *(__nv_bfloat162*)&C[o0] = p0;
                *(__nv_bfloat162*)&C[o1] = p1;
            }
        }
    }
}

// ---------------- weight fp32 -> bf16 ----------------------------------------
__global__ void cvt_w_kernel(const float* __restrict__ qw, const float* __restrict__ kw,
                             const float* __restrict__ vw, const float* __restrict__ pw) {
    int i = blockIdx.x * 256 + threadIdx.x;
    if (i < ND * NC) {
        g_wq[i] = __float2bfloat16(qw[i]);
        g_wk[i] = __float2bfloat16(kw[i]);
        g_wv[i] = __float2bfloat16(vw[i]);
        g_wp[i] = __float2bfloat16(pw[i]);
    }
}

// ---------------- GN phase 1: per-(b,g) stats ---------------------------------
__global__ __launch_bounds__(256) void gn_stats_kernel(const float* __restrict__ x) {
    int bg = blockIdx.x;
    int b = bg >> 5, g = bg & 31;
    const float4* xp = (const float4*)(x + ((size_t)(b * NC + g * 16)) * NN_);
    int t = threadIdx.x;
    float s = 0.f, ss = 0.f;
    for (int i = t; i < 16384; i += 256) {
        float4 v = xp[i];
        s  += v.x + v.y + v.z + v.w;
        ss += v.x * v.x + v.y * v.y + v.z * v.z + v.w * v.w;
    }
    __shared__ float rs[256], rq[256];
    rs[t] = s; rq[t] = ss;
    __syncthreads();
    for (int st = 128; st > 0; st >>= 1) {
        if (t < st) { rs[t] += rs[t + st]; rq[t] += rq[t + st]; }
        __syncthreads();
    }
    if (t == 0) {
        float mean = rs[0] * (1.f / 65536.f);
        float var  = rq[0] * (1.f / 65536.f) - mean * mean;
        g_stats[bg] = make_float2(mean, rsqrtf(var + 1e-5f));
    }
}

// ---------------- GN phase 2: normalize + transpose -> hT [b][n][c] -----------
__global__ __launch_bounds__(256) void gn_apply_kernel(
    const float* __restrict__ x, const float* __restrict__ gamma,
    const float* __restrict__ beta)
{
    __shared__ __align__(16) bf16 ts[128][72];
    int n0 = blockIdx.x * 128, c0 = blockIdx.y * 64, b = blockIdx.z;
    int t = threadIdx.x;
#pragma unroll
    for (int u = 0; u < 8; u++) {
        int idx = t + u * 256;               // 2048 = 64c x 32 (n in float4)
        int c = idx >> 5, nv = idx & 31;
        float2 st = g_stats[b * 32 + ((c0 + c) >> 4)];
        float sc = gamma[c0 + c] * st.y;
        float sh = beta[c0 + c] - st.x * sc;
        float4 v = *(const float4*)(x + ((size_t)(b * NC + c0 + c)) * NN_ + n0 + nv * 4);
        ts[nv * 4 + 0][c] = __float2bfloat16(v.x * sc + sh);
        ts[nv * 4 + 1][c] = __float2bfloat16(v.y * sc + sh);
        ts[nv * 4 + 2][c] = __float2bfloat16(v.z * sc + sh);
        ts[nv * 4 + 3][c] = __float2bfloat16(v.w * sc + sh);
    }
    __syncthreads();
#pragma unroll
    for (int u = 0; u < 4; u++) {
        int idx = t + u * 256;               // 1024 = 128n x 8 (c in uint4)
        int n = idx >> 3, cq = idx & 7;
        uint4 val = *(uint4*)&ts[n][cq * 8];
        *(uint4*)&g_hT[((size_t)(b * NN_ + n0 + n)) * NC + c0 + cq * 8] = val;
    }
}

// ---------------- softmax in place over bf16 S rows ---------------------------
__global__ __launch_bounds__(256) void softmax_kernel() {
    size_t row = blockIdx.x;
    uint4* sp = (uint4*)(g_S + row * NN_);   // 512 uint4 per row
    int t = threadIdx.x;
    uint4 v0 = sp[t], v1 = sp[t + 256];
    float e[16];
    {
        const uint32_t* w0 = (const uint32_t*)&v0;
        const uint32_t* w1 = (const uint32_t*)&v1;
#pragma unroll
        for (int i = 0; i < 4; i++) {
            float2 a = __bfloat1622float2(*(__nv_bfloat162*)&w0[i]);
            e[2 * i] = a.x; e[2 * i + 1] = a.y;
            float2 c = __bfloat1622float2(*(__nv_bfloat162*)&w1[i]);
            e[8 + 2 * i] = c.x; e[8 + 2 * i + 1] = c.y;
        }
    }
    float mx = -1e30f;
#pragma unroll
    for (int i = 0; i < 16; i++) mx = fmaxf(mx, e[i]);
    __shared__ float red[256];
    red[t] = mx; __syncthreads();
    for (int st = 128; st > 0; st >>= 1) {
        if (t < st) red[t] = fmaxf(red[t], red[t + st]);
        __syncthreads();
    }
    float m = red[0];
    __syncthreads();
    float sum = 0.f;
#pragma unroll
    for (int i = 0; i < 16; i++) { e[i] = __expf(e[i] - m); sum += e[i]; }
    red[t] = sum; __syncthreads();
    for (int st = 128; st > 0; st >>= 1) {
        if (t < st) red[t] += red[t + st];
        __syncthreads();
    }
    float inv = 1.f / red[0];
    uint4 o0, o1;
    uint32_t* w0 = (uint32_t*)&o0;
    uint32_t* w1 = (uint32_t*)&o1;
#pragma unroll
    for (int i = 0; i < 4; i++) {
        __nv_bfloat162 a = __floats2bfloat162_rn(e[2 * i] * inv, e[2 * i + 1] * inv);
        w0[i] = *(uint32_t*)&a;
        __nv_bfloat162 c = __floats2bfloat162_rn(e[8 + 2 * i] * inv, e[9 + 2 * i] * inv);
        w1[i] = *(uint32_t*)&c;
    }
    sp[t] = o0; sp[t + 256] = o1;
}

// ---------------- launch ------------------------------------------------------
static void* sym_addr(const void* s) { void* p = nullptr; cudaGetSymbolAddress(&p, s); return p; }

extern "C" void kernel_launch(void* const* d_in, const int* in_sizes, int n_in,
                              void* d_out, int out_size) {
    const float* x   = (const float*)d_in[0];
    const float* gnw = (const float*)d_in[1];
    const float* gnb = (const float*)d_in[2];
    const float* qw  = (const float*)d_in[3];
    const float* qb  = (const float*)d_in[4];
    const float* kw  = (const float*)d_in[5];
    const float* kb  = (const float*)d_in[6];
    const float* vw  = (const float*)d_in[7];
    const float* vb  = (const float*)d_in[8];
    const float* pw  = (const float*)d_in[9];
    const float* pb  = (const float*)d_in[10];

    bf16* p_hT  = (bf16*)sym_addr(g_hT);
    bf16* p_qT  = (bf16*)sym_addr(g_qT);
    bf16* p_kT  = (bf16*)sym_addr(g_kT);
    bf16* p_v   = (bf16*)sym_addr(g_v);
    bf16* p_S   = (bf16*)sym_addr(g_S);
    bf16* p_hfT = (bf16*)sym_addr(g_hfT);
    bf16* p_wq  = (bf16*)sym_addr(g_wq);
    bf16* p_wk  = (bf16*)sym_addr(g_wk);
    bf16* p_wv  = (bf16*)sym_addr(g_wv);
    bf16* p_wp  = (bf16*)sym_addr(g_wp);

    static bool attr_done = false;
    if (!attr_done) {
        cudaFuncSetAttribute(hm_gemm<0>, cudaFuncAttributeMaxDynamicSharedMemorySize, GEMM_SMEM);
        cudaFuncSetAttribute(hm_gemm<1>, cudaFuncAttributeMaxDynamicSharedMemorySize, GEMM_SMEM);
        cudaFuncSetAttribute(hm_gemm<2>, cudaFuncAttributeMaxDynamicSharedMemorySize, GEMM_SMEM);
        cudaFuncSetAttribute(hm_gemm<4>, cudaFuncAttributeMaxDynamicSharedMemorySize, GEMM_SMEM);
        attr_done = true;
    }

    const long long sT  = (long long)NN_ * ND;   // batch stride for hT/qT/kT/v/hfT
    const long long sSS = (long long)NN_ * NN_;
    const float scale = 0.044194173824159216f;   // 512^-0.5

    cvt_w_kernel<<<1024, 256>>>(qw, kw, vw, pw);
    gn_stats_kernel<<<NB * 32, 256>>>(x);
    gn_apply_kernel<<<dim3(32, 8, NB), 256>>>(x, gnw, gnb);

    // qT[n,d] = hT @ Wq^T + qb[d]   (col bias)
    hm_gemm<0><<<dim3(2, 32, NB), NT, GEMM_SMEM>>>(p_hT, p_wq, p_qT, qb, nullptr,
        NN_, ND, NC, sT, 0, sT, 0, 1.f);
    // kT[m,d] = hT @ Wk^T + kb[d]
    hm_gemm<0><<<dim3(2, 32, NB), NT, GEMM_SMEM>>>(p_hT, p_wk, p_kT, kb, nullptr,
        NN_, ND, NC, sT, 0, sT, 0, 1.f);
    // v[d,m] = Wv @ hT^T + vb[d]    (row bias)
    hm_gemm<1><<<dim3(16, 4, NB), NT, GEMM_SMEM>>>(p_wv, p_hT, p_v, vb, nullptr,
        ND, NN_, NC, 0, sT, sT, 0, 1.f);
    // S[n,m] = scale * qT @ kT^T    (bf16)
    hm_gemm<2><<<dim3(16, 32, NB), NT, GEMM_SMEM>>>(p_qT, p_kT, p_S, nullptr, nullptr,
        NN_, NN_, ND, sT, sT, sSS, 0, scale);
    // P = softmax(S) in place
    softmax_kernel<<<NB * NN_, 256>>>();
    // hfT[n,d] = P @ v^T
    hm_gemm<2><<<dim3(2, 32, NB), NT, GEMM_SMEM>>>(p_S, p_v, p_hfT, nullptr, nullptr,
        NN_, ND, NN_, sSS, sT, sT, 0, 1.f);
    // out[c,n] = Wp @ hfT^T + pb[c] + x   (fp32 + residual)
    hm_gemm<4><<<dim3(16, 4, NB), NT, GEMM_SMEM>>>(p_wp, p_hfT, d_out, pb, x,
        NC, NN_, ND, 0, sT, (long long)NC * NN_, (long long)NC * NN_, 1.f);
}

// round 11
// speedup vs baseline: 1.0233x; 1.0233x over previous
#include <cuda_runtime.h>
#include <cuda_bf16.h>
#include <cuda_fp8.h>
#include <cstdint>

typedef __nv_bfloat16 bf16;

// Problem dims: B=8, C=512, H=W=64 -> N=4096, att=512
#define NB 8
#define NC 512
#define NN_ 4096
#define ND 512

// ---------------- scratch (static device globals) ---------------------------
__device__ __align__(1024) bf16    g_hT [(size_t)NB * NN_ * NC];  // [b][n][c] bf16
__device__ __align__(1024) uint8_t g_qT [(size_t)NB * NN_ * ND];  // [b][n][d] fp8
__device__ __align__(1024) uint8_t g_kT [(size_t)NB * NN_ * ND];  // [b][m][d] fp8
__device__ __align__(1024) uint8_t g_v  [(size_t)NB * ND * NN_];  // [b][d][m] fp8
__device__ __align__(1024) uint8_t g_E  [(size_t)NB * NN_ * NN_]; // exp(S) fp8 (128MB)
__device__ __align__(1024) bf16    g_hfT[(size_t)NB * NN_ * ND];  // [b][n][d] bf16
__device__ __align__(1024) bf16    g_wq [ND * NC];
__device__ __align__(1024) bf16    g_wk [ND * NC];
__device__ __align__(1024) bf16    g_wv [ND * NC];
__device__ __align__(1024) bf16    g_wp [NC * ND];
__device__ float  g_rowsum[NB * NN_];                             // softmax denominators
__device__ float2 g_stats [NB * 32];                              // per (b,g): mean, inv

// ---------------- helpers -----------------------------------------------------
__device__ __forceinline__ uint32_t smem_u32(const void* p) {
    uint32_t a;
    asm("{ .reg .u64 t; cvta.to.shared.u64 t, %1; cvt.u32.u64 %0, t; }" : "=r"(a) : "l"(p));
    return a;
}
__device__ __forceinline__ void cp_async16(uint32_t s, const void* g) {
    asm volatile("cp.async.cg.shared.global [%0], [%1], 16;" :: "r"(s), "l"(g));
}
#define CP_COMMIT()  asm volatile("cp.async.commit_group;" ::: "memory")
#define CP_WAIT1()   asm volatile("cp.async.wait_group 1;" ::: "memory")

__device__ __forceinline__ void ldm4(uint32_t* r, uint32_t addr) {
    asm volatile("ldmatrix.sync.aligned.m8n8.x4.shared.b16 {%0,%1,%2,%3}, [%4];"
        : "=r"(r[0]), "=r"(r[1]), "=r"(r[2]), "=r"(r[3]) : "r"(addr));
}
__device__ __forceinline__ void mma16816(float* d, const uint32_t* a, const uint32_t* b) {
    asm volatile(
        "mma.sync.aligned.m16n8k16.row.col.f32.bf16.bf16.f32 "
        "{%0,%1,%2,%3}, {%4,%5,%6,%7}, {%8,%9}, {%0,%1,%2,%3};"
        : "+f"(d[0]), "+f"(d[1]), "+f"(d[2]), "+f"(d[3])
        : "r"(a[0]), "r"(a[1]), "r"(a[2]), "r"(a[3]), "r"(b[0]), "r"(b[1]));
}
__device__ __forceinline__ void mma16832f8(float* d, const uint32_t* a, const uint32_t* b) {
    asm volatile(
        "mma.sync.aligned.m16n8k32.row.col.f32.e4m3.e4m3.f32 "
        "{%0,%1,%2,%3}, {%4,%5,%6,%7}, {%8,%9}, {%0,%1,%2,%3};"
        : "+f"(d[0]), "+f"(d[1]), "+f"(d[2]), "+f"(d[3])
        : "r"(a[0]), "r"(a[1]), "r"(a[2]), "r"(a[3]), "r"(b[0]), "r"(b[1]));
}
__device__ __forceinline__ uint16_t f8x2(float a, float b) {
    __nv_fp8x2_e4m3 p(make_float2(a, b));
    return *(uint16_t*)&p;
}

// ============= bf16 HMMA GEMM: D = A[M,K] @ B[N,K]^T =========================
// CTA tile 128x256x64, 512 threads, 16 warps (2x8), warp tile 64x32.
// OM: 0 = fp8 out + col bias[n]; 1 = fp8 out + row bias[m];
//     4 = fp32 out + row bias[m] + residual.
#define BM 128
#define BN 256
#define BK 64
#define NT 512
#define ROWB 144
#define A_BYTES (BM * ROWB)
#define B_BYTES (BN * ROWB)
#define STAGE_BYTES (A_BYTES + B_BYTES)
#define STAGES 3
#define GEMM_SMEM (STAGES * STAGE_BYTES)

template<int OM>
__global__ __launch_bounds__(NT, 1)
void hm_gemm(const bf16* __restrict__ A, const bf16* __restrict__ B, void* __restrict__ Cv,
             const float* __restrict__ bias, const float* __restrict__ resid,
             int M, int N, int K,
             long long sA, long long sB, long long sC, long long sR, float alpha)
{
    extern __shared__ __align__(16) char smem[];
    int t = threadIdx.x, w = t >> 5, lane = t & 31;
    int wm = w >> 3, wn = w & 7;
    int bz = blockIdx.z;
    const bf16* Ab = A + sA * bz;
    const bf16* Bb = B + sB * bz;
    int bm = blockIdx.y * BM;
    int bn = blockIdx.x * BN;
    uint32_t sbase = smem_u32(smem);

    auto load_chunk = [&](int kc, int s) {
        uint32_t sa = sbase + s * STAGE_BYTES;
        uint32_t sb = sa + A_BYTES;
        int k0 = kc * BK;
#pragma unroll
        for (int u = 0; u < 2; u++) {
            int idx = t + u * NT;
            int r = idx >> 3, c = idx & 7;
            cp_async16(sa + r * ROWB + c * 16, Ab + (size_t)(bm + r) * K + k0 + c * 8);
        }
#pragma unroll
        for (int u = 0; u < 4; u++) {
            int idx = t + u * NT;
            int r = idx >> 3, c = idx & 7;
            cp_async16(sb + r * ROWB + c * 16, Bb + (size_t)(bn + r) * K + k0 + c * 8);
        }
        CP_COMMIT();
    };

    int lr = lane & 7, sub = lane >> 3;
    uint32_t offA = (uint32_t)((wm * 64 + (sub & 1) * 8 + lr) * ROWB + ((sub >> 1) * 8) * 2);
    uint32_t offB = (uint32_t)((wn * 32 + (sub >> 1) * 8 + lr) * ROWB + ((sub & 1) * 8) * 2);

    float acc[4][4][4];
#pragma unroll
    for (int i = 0; i < 4; i++)
#pragma unroll
        for (int j = 0; j < 4; j++)
#pragma unroll
            for (int q = 0; q < 4; q++) acc[i][j][q] = 0.f;

    uint32_t frA[4][4];
    uint32_t frB[2][4];

    int nK = K / BK;
    load_chunk(0, 0); load_chunk(1, 1);

    int s = 0, sp = 2;
    for (int kc = 0; kc < nK; kc++) {
        CP_WAIT1();
        __syncthreads();
        if (kc + 2 < nK) load_chunk(kc + 2, sp);
        else CP_COMMIT();

        uint32_t sb = sbase + s * STAGE_BYTES;
#pragma unroll
        for (int ks = 0; ks < 4; ks++) {
            uint32_t ka = sb + offA + ks * 32;
#pragma unroll
            for (int i = 0; i < 4; i++) ldm4(frA[i], ka + i * 16 * ROWB);
            uint32_t kb = sb + A_BYTES + offB + ks * 32;
#pragma unroll
            for (int j = 0; j < 2; j++) ldm4(frB[j], kb + j * 16 * ROWB);
#pragma unroll
            for (int i = 0; i < 4; i++)
#pragma unroll
                for (int jj = 0; jj < 4; jj++)
                    mma16816(acc[i][jj], frA[i], &frB[jj >> 1][(jj & 1) * 2]);
        }
        s  = (s  == STAGES - 1) ? 0 : s + 1;
        sp = (sp == STAGES - 1) ? 0 : sp + 1;
    }

#pragma unroll
    for (int i = 0; i < 4; i++) {
        int r0 = bm + wm * 64 + i * 16 + (lane >> 2);
#pragma unroll
        for (int jj = 0; jj < 4; jj++) {
            int col = bn + wn * 32 + jj * 8 + (lane & 3) * 2;
            float v0 = acc[i][jj][0], v1 = acc[i][jj][1];
            float v2 = acc[i][jj][2], v3 = acc[i][jj][3];
            if (OM == 0) {
                float b0 = bias[col], b1 = bias[col + 1];
                v0 += b0; v1 += b1; v2 += b0; v3 += b1;
            }
            if (OM == 1 || OM == 4) {
                float ba = bias[r0], bb = bias[r0 + 8];
                v0 += ba; v1 += ba; v2 += bb; v3 += bb;
            }
            size_t o0 = (size_t)r0 * N + col;
            size_t o1 = (size_t)(r0 + 8) * N + col;
            if (OM == 4) {
                float* C = (float*)Cv + sC * bz;
                const float* R = resid + sR * bz;
                float2 ra = *(const float2*)&R[o0];
                float2 rb = *(const float2*)&R[o1];
                *(float2*)&C[o0] = make_float2(v0 + ra.x, v1 + ra.y);
                *(float2*)&C[o1] = make_float2(v2 + rb.x, v3 + rb.y);
            } else {
                uint8_t* C = (uint8_t*)Cv + sC * bz;
                *(uint16_t*)&C[o0] = f8x2(v0, v1);
                *(uint16_t*)&C[o1] = f8x2(v2, v3);
            }
        }
    }
}

// ============= fp8 GEMM: D = A[M,K] @ B[N,K]^T (e4m3, fp32 acc) ==============
// CTA tile 128x256x64(bytes), 512 threads, 16 warps (2x8), warp tile 64x32.
// OM: 3 = E = exp(alpha*acc) fp8 out + atomic row sums into rs[]
//     5 = bf16 out, scaled by 1/rs[row]
#define F8_ROWB 80
#define F8_A_BYTES (128 * F8_ROWB)      // 10240
#define F8_B_BYTES (256 * F8_ROWB)      // 20480
#define F8_STAGE (F8_A_BYTES + F8_B_BYTES)
#define F8_STAGES 3
#define F8_SMEM (F8_STAGES * F8_STAGE)  // 92160

template<int OM>
__global__ __launch_bounds__(NT, 1)
void f8_gemm(const uint8_t* __restrict__ A, const uint8_t* __restrict__ B,
             void* __restrict__ Cv, float* __restrict__ rs_base,
             int M, int N, int K,
             long long sA, long long sB, long long sC, long long sRS, float alpha)
{
    extern __shared__ __align__(16) char smem[];
    int t = threadIdx.x, w = t >> 5, lane = t & 31;
    int wm = w >> 3, wn = w & 7;
    int bz = blockIdx.z;
    const uint8_t* Ab = A + sA * bz;
    const uint8_t* Bb = B + sB * bz;
    float* rs = rs_base + sRS * bz;
    int bm = blockIdx.y * 128;
    int bn = blockIdx.x * 256;
    uint32_t sbase = smem_u32(smem);

    // chunk = 64 bytes of K. A: 128 rows x 4x16B = 512 cp (1/thr); B: 256 rows (2/thr)
    auto load_chunk = [&](int kc, int s) {
        uint32_t sa = sbase + s * F8_STAGE;
        uint32_t sb = sa + F8_A_BYTES;
        int k0 = kc * 64;
        {
            int r = t >> 2, c = t & 3;
            cp_async16(sa + r * F8_ROWB + c * 16, Ab + (size_t)(bm + r) * K + k0 + c * 16);
        }
#pragma unroll
        for (int u = 0; u < 2; u++) {
            int idx = t + u * NT;
            int r = idx >> 2, c = idx & 3;
            cp_async16(sb + r * F8_ROWB + c * 16, Bb + (size_t)(bn + r) * K + k0 + c * 16);
        }
        CP_COMMIT();
    };

    int lr = lane & 7, sub = lane >> 3;
    uint32_t offA = (uint32_t)((wm * 64 + (sub & 1) * 8 + lr) * F8_ROWB + (sub >> 1) * 16);
    uint32_t offB = (uint32_t)((wn * 32 + (sub >> 1) * 8 + lr) * F8_ROWB + (sub & 1) * 16);

    float acc[4][4][4];
#pragma unroll
    for (int i = 0; i < 4; i++)
#pragma unroll
        for (int j = 0; j < 4; j++)
#pragma unroll
            for (int q = 0; q < 4; q++) acc[i][j][q] = 0.f;

    uint32_t frA[4][4];
    uint32_t frB[2][4];

    int nK = K / 64;
    load_chunk(0, 0); load_chunk(1, 1);

    int s = 0, sp = 2;
    for (int kc = 0; kc < nK; kc++) {
        CP_WAIT1();
        __syncthreads();
        if (kc + 2 < nK) load_chunk(kc + 2, sp);
        else CP_COMMIT();

        uint32_t sb = sbase + s * F8_STAGE;
#pragma unroll
        for (int ks = 0; ks < 2; ks++) {       // 2 x k32 per 64B chunk
            uint32_t ka = sb + offA + ks * 32;
#pragma unroll
            for (int i = 0; i < 4; i++) ldm4(frA[i], ka + i * 16 * F8_ROWB);
            uint32_t kb = sb + F8_A_BYTES + offB + ks * 32;
#pragma unroll
            for (int j = 0; j < 2; j++) ldm4(frB[j], kb + j * 16 * F8_ROWB);
#pragma unroll
            for (int i = 0; i < 4; i++)
#pragma unroll
                for (int jj = 0; jj < 4; jj++)
                    mma16832f8(acc[i][jj], frA[i], &frB[jj >> 1][(jj & 1) * 2]);
        }
        s  = (s  == F8_STAGES - 1) ? 0 : s + 1;
        sp = (sp == F8_STAGES - 1) ? 0 : sp + 1;
    }

    // ---------------- epilogue ------------------------------------------------
#pragma unroll
    for (int i = 0; i < 4; i++) {
        int r0 = bm + wm * 64 + i * 16 + (lane >> 2);
        if (OM == 3) {
            float pr0 = 0.f, pr8 = 0.f;
#pragma unroll
            for (int jj = 0; jj < 4; jj++) {
                int col = bn + wn * 32 + jj * 8 + (lane & 3) * 2;
                float e0 = __expf(alpha * acc[i][jj][0]);
                float e1 = __expf(alpha * acc[i][jj][1]);
                float e2 = __expf(alpha * acc[i][jj][2]);
                float e3 = __expf(alpha * acc[i][jj][3]);
                pr0 += e0 + e1; pr8 += e2 + e3;
                uint8_t* C = (uint8_t*)Cv + sC * bz;
                *(uint16_t*)&C[(size_t)r0 * N + col]       = f8x2(e0, e1);
                *(uint16_t*)&C[(size_t)(r0 + 8) * N + col] = f8x2(e2, e3);
            }
            pr0 += __shfl_xor_sync(0xFFFFFFFFu, pr0, 1);
            pr0 += __shfl_xor_sync(0xFFFFFFFFu, pr0, 2);
            pr8 += __shfl_xor_sync(0xFFFFFFFFu, pr8, 1);
            pr8 += __shfl_xor_sync(0xFFFFFFFFu, pr8, 2);
            if ((lane & 3) == 0) {
                atomicAdd(&rs[r0], pr0);
                atomicAdd(&rs[r0 + 8], pr8);
            }
        } else { // OM == 5
            float inv0 = 1.0f / rs[r0];
            float inv8 = 1.0f / rs[r0 + 8];
#pragma unroll
            for (int jj = 0; jj < 4; jj++) {
                int col = bn + wn * 32 + jj * 8 + (lane & 3) * 2;
                bf16* C = (bf16*)Cv + sC * bz;
                *(__nv_bfloat162*)&C[(size_t)r0 * N + col] =
                    __floats2bfloat162_rn(acc[i][jj][0] * inv0, acc[i][jj][1] * inv0);
                *(__nv_bfloat162*)&C[(size_t)(r0 + 8) * N + col] =
                    __floats2bfloat162_rn(acc[i][jj][2] * inv8, acc[i][jj][3] * inv8);
            }
        }
    }
}

// ---------------- weight fp32 -> bf16, zero rowsums ---------------------------
__global__ void cvt_w_kernel(const float* __restrict__ qw, const float* __restrict__ kw,
                             const float* __restrict__ vw, const float* __restrict__ pw) {
    int i = blockIdx.x * 256 + threadIdx.x;
    if (i < ND * NC) {
        g_wq[i] = __float2bfloat16(qw[i]);
        g_wk[i] = __float2bfloat16(kw[i]);
        g_wv[i] = __float2bfloat16(vw[i]);
        g_wp[i] = __float2bfloat16(pw[i]);
    }
    if (i < NB * NN_) g_rowsum[i] = 0.f;
}

// ---------------- GN phase 1: per-(b,g) stats ---------------------------------
__global__ __launch_bounds__(256) void gn_stats_kernel(const float* __restrict__ x) {
    int bg = blockIdx.x;
    int b = bg >> 5, g = bg & 31;
    const float4* xp = (const float4*)(x + ((size_t)(b * NC + g * 16)) * NN_);
    int t = threadIdx.x;
    float s = 0.f, ss = 0.f;
    for (int i = t; i < 16384; i += 256) {
        float4 v = xp[i];
        s  += v.x + v.y + v.z + v.w;
        ss += v.x * v.x + v.y * v.y + v.z * v.z + v.w * v.w;
    }
    __shared__ float rs[256], rq[256];
    rs[t] = s; rq[t] = ss;
    __syncthreads();
    for (int st = 128; st > 0; st >>= 1) {
        if (t < st) { rs[t] += rs[t + st]; rq[t] += rq[t + st]; }
        __syncthreads();
    }
    if (t == 0) {
        float mean = rs[0] * (1.f / 65536.f);
        float var  = rq[0] * (1.f / 65536.f) - mean * mean;
        g_stats[bg] = make_float2(mean, rsqrtf(var + 1e-5f));
    }
}

// ---------------- GN phase 2: normalize + transpose -> hT [b][n][c] -----------
__global__ __launch_bounds__(256) void gn_apply_kernel(
    const float* __restrict__ x, const float* __restrict__ gamma,
    const float* __restrict__ beta)
{
    __shared__ __align__(16) bf16 ts[128][72];
    int n0 = blockIdx.x * 128, c0 = blockIdx.y * 64, b = blockIdx.z;
    int t = threadIdx.x;
#pragma unroll
    for (int u = 0; u < 8; u++) {
        int idx = t + u * 256;
        int c = idx >> 5, nv = idx & 31;
        float2 st = g_stats[b * 32 + ((c0 + c) >> 4)];
        float sc = gamma[c0 + c] * st.y;
        float sh = beta[c0 + c] - st.x * sc;
        float4 v = *(const float4*)(x + ((size_t)(b * NC + c0 + c)) * NN_ + n0 + nv * 4);
        ts[nv * 4 + 0][c] = __float2bfloat16(v.x * sc + sh);
        ts[nv * 4 + 1][c] = __float2bfloat16(v.y * sc + sh);
        ts[nv * 4 + 2][c] = __float2bfloat16(v.z * sc + sh);
        ts[nv * 4 + 3][c] = __float2bfloat16(v.w * sc + sh);
    }
    __syncthreads();
#pragma unroll
    for (int u = 0; u < 4; u++) {
        int idx = t + u * 256;
        int n = idx >> 3, cq = idx & 7;
        uint4 val = *(uint4*)&ts[n][cq * 8];
        *(uint4*)&g_hT[((size_t)(b * NN_ + n0 + n)) * NC + c0 + cq * 8] = val;
    }
}

// ---------------- launch ------------------------------------------------------
static void* sym_addr(const void* s) { void* p = nullptr; cudaGetSymbolAddress(&p, s); return p; }

extern "C" void kernel_launch(void* const* d_in, const int* in_sizes, int n_in,
                              void* d_out, int out_size) {
    const float* x   = (const float*)d_in[0];
    const float* gnw = (const float*)d_in[1];
    const float* gnb = (const float*)d_in[2];
    const float* qw  = (const float*)d_in[3];
    const float* qb  = (const float*)d_in[4];
    const float* kw  = (const float*)d_in[5];
    const float* kb  = (const float*)d_in[6];
    const float* vw  = (const float*)d_in[7];
    const float* vb  = (const float*)d_in[8];
    const float* pw  = (const float*)d_in[9];
    const float* pb  = (const float*)d_in[10];

    bf16*    p_hT  = (bf16*)   sym_addr(g_hT);
    uint8_t* p_qT  = (uint8_t*)sym_addr(g_qT);
    uint8_t* p_kT  = (uint8_t*)sym_addr(g_kT);
    uint8_t* p_v   = (uint8_t*)sym_addr(g_v);
    uint8_t* p_E   = (uint8_t*)sym_addr(g_E);
    bf16*    p_hfT = (bf16*)   sym_addr(g_hfT);
    bf16*    p_wq  = (bf16*)   sym_addr(g_wq);
    bf16*    p_wk  = (bf16*)   sym_addr(g_wk);
    bf16*    p_wv  = (bf16*)   sym_addr(g_wv);
    bf16*    p_wp  = (bf16*)   sym_addr(g_wp);
    float*   p_rs  = (float*)  sym_addr(g_rowsum);

    static bool attr_done = false;
    if (!attr_done) {
        cudaFuncSetAttribute(hm_gemm<0>, cudaFuncAttributeMaxDynamicSharedMemorySize, GEMM_SMEM);
        cudaFuncSetAttribute(hm_gemm<1>, cudaFuncAttributeMaxDynamicSharedMemorySize, GEMM_SMEM);
        cudaFuncSetAttribute(hm_gemm<4>, cudaFuncAttributeMaxDynamicSharedMemorySize, GEMM_SMEM);
        cudaFuncSetAttribute(f8_gemm<3>, cudaFuncAttributeMaxDynamicSharedMemorySize, F8_SMEM);
        cudaFuncSetAttribute(f8_gemm<5>, cudaFuncAttributeMaxDynamicSharedMemorySize, F8_SMEM);
        attr_done = true;
    }

    const long long sT  = (long long)NN_ * ND;   // 2^21
    const long long sSS = (long long)NN_ * NN_;  // 2^24
    const float scale = 0.044194173824159216f;   // 512^-0.5

    cvt_w_kernel<<<1024, 256>>>(qw, kw, vw, pw);
    gn_stats_kernel<<<NB * 32, 256>>>(x);
    gn_apply_kernel<<<dim3(32, 8, NB), 256>>>(x, gnw, gnb);

    // qT[n,d] = hT @ Wq^T + qb[d]  -> fp8
    hm_gemm<0><<<dim3(2, 32, NB), NT, GEMM_SMEM>>>(p_hT, p_wq, p_qT, qb, nullptr,
        NN_, ND, NC, sT, 0, sT, 0, 1.f);
    // kT[m,d] = hT @ Wk^T + kb[d]  -> fp8
    hm_gemm<0><<<dim3(2, 32, NB), NT, GEMM_SMEM>>>(p_hT, p_wk, p_kT, kb, nullptr,
        NN_, ND, NC, sT, 0, sT, 0, 1.f);
    // v[d,m] = Wv @ hT^T + vb[d]   -> fp8
    hm_gemm<1><<<dim3(16, 4, NB), NT, GEMM_SMEM>>>(p_wv, p_hT, p_v, vb, nullptr,
        ND, NN_, NC, 0, sT, sT, 0, 1.f);
    // E[n,m] = exp(scale * qT @ kT^T), rowsum accumulated (fp8 GEMM)
    f8_gemm<3><<<dim3(16, 32, NB), NT, F8_SMEM>>>(p_qT, p_kT, p_E, p_rs,
        NN_, NN_, ND, sT, sT, sSS, NN_, scale);
    // hfT[n,d] = (E @ v^T) / rowsum[n]  (fp8 GEMM, bf16 out)
    f8_gemm<5><<<dim3(2, 32, NB), NT, F8_SMEM>>>(p_E, p_v, p_hfT, p_rs,
        NN_, ND, NN_, sSS, sT, sT, NN_, 1.f);
    // out[c,n] = Wp @ hfT^T + pb[c] + x   (fp32 + residual)
    hm_gemm<4><<<dim3(16, 4, NB), NT, GEMM_SMEM>>>(p_wp, p_hfT, d_out, pb, x,
        NC, NN_, ND, 0, sT, (long long)NC * NN_, (long long)NC * NN_, 1.f);
}